// round 16
// baseline (speedup 1.0000x reference)
#include <cuda_runtime.h>
#include <cuda_bf16.h>
#include <math.h>
#include <stdint.h>

#define BB 8
#define NP 2048
#define KNNK 20

// ---------------- static scratch (no allocations allowed) ----------------
__device__ __align__(16) float d_xt   [BB * NP * 3];
__device__ __align__(16) float d_feats[BB * NP * 512];   // x1|x2|x3|x4 at ch 0/64/128/256
__device__ __align__(16) float d_yz   [BB * NP * 512];   // per-layer [Y|Z], 2O <= 512
__device__ __align__(16) float d_x5   [BB * NP * 1024];
__device__            int    d_idx  [BB * NP * KNNK];
__device__ __align__(16) float d_map2 [BB * 2080];
__device__ __align__(16) float d_h1   [BB * 512];
__device__ __align__(16) float d_h2   [BB * 256];
// folded weights
__device__ __align__(16) float d_WC1[2 * 64 * 3];
__device__ __align__(16) float d_WC2[2 * 64 * 64];
__device__ __align__(16) float d_WC3[2 * 128 * 64];
__device__ __align__(16) float d_WC4[2 * 256 * 128];
__device__ __align__(16) float d_W5f[1024 * 512];
__device__ __align__(16) float d_W6f[512 * 2080];
__device__ __align__(16) float d_b6f[512];
__device__ __align__(16) float d_W7f[256 * 512];
__device__ __align__(16) float d_b7f[256];
__device__ __align__(16) float d_Wpf[32 * 8];
__device__ __align__(16) float d_bpf[32];

__device__ __forceinline__ float lrelu(float v) { return v >= 0.f ? v : 0.2f * v; }

// packed fp32x2 helpers (Blackwell FFMA2)
#define FMA2(acc, a, b) asm("fma.rn.f32x2 %0, %1, %2, %0;" : "+l"(acc) : "l"(a), "l"(b))
__device__ __forceinline__ unsigned long long dup2(float w) {
    unsigned long long r;
    asm("mov.b64 %0, {%1, %1};" : "=l"(r) : "f"(w));
    return r;
}
__device__ __forceinline__ unsigned long long pack2(float a, float b) {
    unsigned long long r;
    asm("mov.b64 %0, {%1, %2};" : "=l"(r) : "f"(a), "f"(b));
    return r;
}
__device__ __forceinline__ float2 unpack2(unsigned long long v) {
    float2 f;
    asm("mov.b64 {%0, %1}, %2;" : "=f"(f.x), "=f"(f.y) : "l"(v));
    return f;
}

// ---------------- merged weight folding (edge convs) ----------------
__device__ __forceinline__ void fold_edge(const float* W, const float* g,
                                          float* Wcat, int O, int C, int e)
{
    int o = e / C, c = e % C;
    float s = g[o] * rsqrtf(1.0f + 1e-5f);
    float wa = W[o * 2 * C + c];
    float wb = W[o * 2 * C + C + c];
    Wcat[o * C + c] = s * wa;
    Wcat[(O + o) * C + c] = s * (wb - wa);
}

#define NE1 (64 * 3)
#define NE2 (64 * 64)
#define NE3 (128 * 64)
#define NE4 (256 * 128)

__global__ void prep_edge_all_k(const float* __restrict__ W1, const float* __restrict__ g1,
                                const float* __restrict__ W2, const float* __restrict__ g2,
                                const float* __restrict__ W3, const float* __restrict__ g3,
                                const float* __restrict__ W4, const float* __restrict__ g4,
                                float* __restrict__ WC1, float* __restrict__ WC2,
                                float* __restrict__ WC3, float* __restrict__ WC4)
{
    int e = blockIdx.x * blockDim.x + threadIdx.x;
    if (e < NE1) { fold_edge(W1, g1, WC1, 64, 3, e); return; }
    e -= NE1;
    if (e < NE2) { fold_edge(W2, g2, WC2, 64, 64, e); return; }
    e -= NE2;
    if (e < NE3) { fold_edge(W3, g3, WC3, 128, 64, e); return; }
    e -= NE3;
    if (e < NE4) { fold_edge(W4, g4, WC4, 256, 128, e); return; }
}

// ---------------- merged fc/scale folding ----------------
#define NF5 (1024 * 512)
#define NF6 (512 * 2080)
#define NF7 (256 * 512)
#define NFP (32 * 6)

__global__ void prep_fc_all_k(const float* __restrict__ W5, const float* __restrict__ g5,
                              const float* __restrict__ WL1, const float* __restrict__ bL1,
                              const float* __restrict__ g6, const float* __restrict__ b6,
                              const float* __restrict__ WL2, const float* __restrict__ bL2,
                              const float* __restrict__ g7, const float* __restrict__ b7,
                              const float* __restrict__ Wp, const float* __restrict__ bp,
                              const float* __restrict__ gp, const float* __restrict__ bpb,
                              float* __restrict__ W5f,
                              float* __restrict__ W6f, float* __restrict__ b6f,
                              float* __restrict__ W7f, float* __restrict__ b7f,
                              float* __restrict__ Wpf, float* __restrict__ bpf)
{
    int e = blockIdx.x * blockDim.x + threadIdx.x;
    if (e < NF5) {
        int o = e / 512;
        W5f[e] = (g5[o] * rsqrtf(1.0f + 1e-5f)) * W5[e];
        return;
    }
    e -= NF5;
    if (e < NF6) {
        int o = e / 2080, c = e % 2080;
        float s = g6[o] * rsqrtf(1.0f + 1e-5f);
        W6f[e] = s * WL1[e];
        if (c == 0) b6f[o] = s * bL1[o] + b6[o];
        return;
    }
    e -= NF6;
    if (e < NF7) {
        int o = e / 512, c = e % 512;
        float s = g7[o] * rsqrtf(1.0f + 1e-5f);
        W7f[e] = s * WL2[e];
        if (c == 0) b7f[o] = s * bL2[o] + b7[o];
        return;
    }
    e -= NF7;
    if (e < NFP) {
        int o = e / 6, c = e % 6;
        float s = gp[o] * rsqrtf(1.0f + 1e-5f);
        Wpf[o * 8 + c] = s * Wp[e];
        if (c == 0) bpf[o] = s * bp[o] + bpb[o];
        return;
    }
}

// ---------------- transpose (B,3,N) -> (B,N,3) ----------------
__global__ void transpose_k(const float* __restrict__ x, float* __restrict__ xt)
{
    int gid = blockIdx.x * blockDim.x + threadIdx.x;
    if (gid >= BB * 3 * NP) return;
    int n = gid % NP;
    int c = (gid / NP) % 3;
    int b = gid / (3 * NP);
    xt[(b * NP + n) * 3 + c] = x[gid];
}

// ---------------- fused distance + top-20 KNN ----------------
// TI queries/block, TQ threads/query (NT warps = NP*BB*TQ/32), j streamed in
// JT-row tiles. Conflict-free padded strides; norms in-kernel with identical
// FMA2 chains so self-distance is exactly 0. Warp-synchronized insert with
// 4-slot register stash (ballot per candidate, flush-all when any lane fills).
template <int C> struct KnnPad { static constexpr int Cp = C + 4; };
template <> struct KnnPad<3>   { static constexpr int Cp = 4; };
template <> struct KnnPad<64>  { static constexpr int Cp = 76; };
template <> struct KnnPad<128> { static constexpr int Cp = 132; };

template <int C, int TI, int TQ, int JT>
__global__ void __launch_bounds__(TI * TQ, 3)
knn_k(const float* __restrict__ in, int instride, int inoff, int* __restrict__ idxout)
{
    constexpr int Cp  = KnnPad<C>::Cp;
    constexpr int NT  = TI * TQ;
    constexpr int JPT = JT / TQ;
    constexpr int JB  = (JPT < 8) ? JPT : 8;
    constexpr int QS  = (C == 3) ? 0 : TI * Cp;
    extern __shared__ float sm[];
    float* s_xi  = sm;
    float* s_xj  = sm + QS;
    float* s_xxi = s_xj + JT * Cp;
    float* s_xxj = s_xxi + TI;

    const int b  = blockIdx.y;
    const int n0 = blockIdx.x * TI;
    const int t  = threadIdx.x;
    const int i  = t % TI;
    const int q  = t / TI;

    // ---- query + its norm (identical FMA2 pairing as the dot path)
    unsigned long long aq0 = 0ull, aq1 = 0ull;
    float xxi;
    if (C == 3) {
        const float* qp = in + (size_t)(b * NP + n0 + i) * instride + inoff;
        aq0 = pack2(qp[0], qp[1]);
        aq1 = pack2(qp[2], 0.f);
        unsigned long long acc = 0ull;
        FMA2(acc, aq0, aq0);
        FMA2(acc, aq1, aq1);
        float2 f = unpack2(acc);
        xxi = f.x + f.y;
    } else {
        for (int e = t; e < TI * C / 4; e += NT) {
            int r = e / (C / 4), c4 = e % (C / 4);
            *(float4*)&s_xi[r * Cp + 4 * c4] =
                *(const float4*)(in + (size_t)(b * NP + n0 + r) * instride + inoff + 4 * c4);
        }
        __syncthreads();
        if (t < TI) {
            unsigned long long acc = 0ull;
#pragma unroll
            for (int c4 = 0; c4 < C / 4; c4++) {
                ulonglong2 a = *(const ulonglong2*)&s_xi[t * Cp + 4 * c4];
                FMA2(acc, a.x, a.x);
                FMA2(acc, a.y, a.y);
            }
            float2 f = unpack2(acc);
            s_xxi[t] = f.x + f.y;
        }
        __syncthreads();
        xxi = s_xxi[i];
    }

    float kv[KNNK];
    int   kj[KNNK];
#pragma unroll
    for (int s = 0; s < KNNK; s++) { kv[s] = -3.4e38f; kj[s] = 0x7fffffff; }

    // 4-slot register stash
    float s0v = 0.f, s1v = 0.f, s2v = 0.f, s3v = 0.f;
    int   s0j = 0,   s1j = 0,   s2j = 0,   s3j = 0,   scnt = 0;

    auto flush = [&]() {
#pragma unroll
        for (int slot = 0; slot < 4; slot++) {
            float nv = (slot == 0) ? s0v : (slot == 1) ? s1v : (slot == 2) ? s2v : s3v;
            int   nj = (slot == 0) ? s0j : (slot == 1) ? s1j : (slot == 2) ? s2j : s3j;
            bool a = (scnt > slot) && (nv > kv[KNNK - 1]);
            kv[KNNK - 1] = a ? nv : kv[KNNK - 1];
            kj[KNNK - 1] = a ? nj : kj[KNNK - 1];
#pragma unroll
            for (int s = KNNK - 1; s > 0; s--) {
                bool sw = kv[s] > kv[s - 1];
                float tv = kv[s - 1]; int tj = kj[s - 1];
                kv[s - 1] = sw ? kv[s] : tv;
                kj[s - 1] = sw ? kj[s] : tj;
                kv[s]     = sw ? tv : kv[s];
                kj[s]     = sw ? tj : kj[s];
            }
        }
        scnt = 0;
    };

    auto accept = [&](float pd, int j) {
        bool ac = pd > kv[KNNK - 1];
        bool h0 = ac && (scnt == 0);
        bool h1 = ac && (scnt == 1);
        bool h2 = ac && (scnt == 2);
        bool h3 = ac && (scnt == 3);
        s0v = h0 ? pd : s0v;  s0j = h0 ? j : s0j;
        s1v = h1 ? pd : s1v;  s1j = h1 ? j : s1j;
        s2v = h2 ? pd : s2v;  s2j = h2 ? j : s2j;
        s3v = h3 ? pd : s3v;  s3j = h3 ? j : s3j;
        scnt += ac ? 1 : 0;
        if (__ballot_sync(0xffffffffu, scnt >= 4)) flush();
    };

    for (int j0 = 0; j0 < NP; j0 += JT) {
        __syncthreads();
        if (C == 3) {
            for (int e = t; e < JT; e += NT) {
                const float* rp = in + (size_t)(b * NP + j0 + e) * instride + inoff;
                float v0 = rp[0], v1 = rp[1], v2 = rp[2];
                s_xj[e * 4 + 0] = v0;
                s_xj[e * 4 + 1] = v1;
                s_xj[e * 4 + 2] = v2;
                s_xj[e * 4 + 3] = 0.f;
                float sx = 0.f, sy = 0.f;
                sx += v0 * v0;
                sy += v1 * v1;
                sx += v2 * v2;
                s_xxj[e] = sx + sy;
            }
            __syncthreads();
        } else {
            for (int e = t; e < JT * C / 4; e += NT) {
                int r = e / (C / 4), c4 = e % (C / 4);
                *(float4*)&s_xj[r * Cp + 4 * c4] =
                    *(const float4*)(in + (size_t)(b * NP + j0 + r) * instride + inoff + 4 * c4);
            }
            __syncthreads();
            if (t < JT) {
                unsigned long long acc = 0ull;
#pragma unroll
                for (int c4 = 0; c4 < C / 4; c4++) {
                    ulonglong2 a = *(const ulonglong2*)&s_xj[t * Cp + 4 * c4];
                    FMA2(acc, a.x, a.x);
                    FMA2(acc, a.y, a.y);
                }
                float2 f = unpack2(acc);
                s_xxj[t] = f.x + f.y;
            }
            __syncthreads();
        }

        if (C == 3) {
#pragma unroll 1
            for (int jj = 0; jj < JPT; jj++) {
                int jl = q * JPT + jj;
                ulonglong2 w = *(const ulonglong2*)&s_xj[jl * 4];
                unsigned long long acc = 0ull;
                FMA2(acc, aq0, w.x);
                FMA2(acc, aq1, w.y);
                float2 f = unpack2(acc);
                float pd = 2.f * (f.x + f.y) - xxi - s_xxj[jl];
                accept(pd, j0 + jl);
            }
        } else {
            // sub-batch jj in chunks of JB to bound dacc register pressure
#pragma unroll 1
            for (int jb = 0; jb < JPT; jb += JB) {
                unsigned long long dacc[JB];
#pragma unroll
                for (int jj = 0; jj < JB; jj++) dacc[jj] = 0ull;
#pragma unroll 2
                for (int c4 = 0; c4 < C / 4; c4++) {
                    ulonglong2 a = *(const ulonglong2*)&s_xi[i * Cp + 4 * c4];
#pragma unroll
                    for (int jj = 0; jj < JB; jj++) {
                        ulonglong2 w = *(const ulonglong2*)&s_xj[(q * JPT + jb + jj) * Cp + 4 * c4];
                        FMA2(dacc[jj], a.x, w.x);
                        FMA2(dacc[jj], a.y, w.y);
                    }
                }
#pragma unroll 1
                for (int jj = 0; jj < JB; jj++) {
                    int jl = q * JPT + jb + jj;
                    float2 f = unpack2(dacc[jj]);
                    float pd = 2.f * (f.x + f.y) - xxi - s_xxj[jl];
                    accept(pd, j0 + jl);
                }
            }
        }
    }

    flush();  // drain residual stash

    __syncthreads();  // reuse smem for merge
    float* s_mv = sm;
    int*   s_mi = (int*)(sm + NT * KNNK);
    {
        int base = (i * TQ + q) * KNNK;
#pragma unroll
        for (int s = 0; s < KNNK; s++) { s_mv[base + s] = kv[s]; s_mi[base + s] = kj[s]; }
    }
    __syncthreads();

    if (t < TI) {
        int base = t * TQ * KNNK;
        int p[TQ];
#pragma unroll
        for (int qq = 0; qq < TQ; qq++) p[qq] = 0;
        int* orow = idxout + (size_t)(b * NP + n0 + t) * KNNK;
        for (int s = 0; s < KNNK; s++) {
            float bv = -3.4e38f; int bj = 0x7fffffff; int bq = 0;
#pragma unroll
            for (int qq = 0; qq < TQ; qq++) {
                float v  = s_mv[base + qq * KNNK + p[qq]];
                int   jv = s_mi[base + qq * KNNK + p[qq]];
                if (v > bv || (v == bv && jv < bj)) { bv = v; bj = jv; bq = qq; }
            }
            orow[s] = bj;
#pragma unroll
            for (int qq = 0; qq < TQ; qq++) p[qq] += (bq == qq) ? 1 : 0;
        }
    }
}

// ---------------- FFMA2 GEMM: out[M x Nout] = A[M x K] @ W[Nout x K]^T ----
template <int MODE>
__global__ void __launch_bounds__(256, 2)
gemm2_k(const float* __restrict__ A, int astride, int aoff,
        const float* __restrict__ W, const float* __restrict__ bias,
        float* __restrict__ out, int K, int Nout)
{
    __shared__ __align__(16) float As[2][16][132];
    __shared__ __align__(16) float Ws[2][16][132];
    const int m0 = blockIdx.y * 128, n0 = blockIdx.x * 128;
    const int t  = threadIdx.x;
    const int tx = t % 16, ty = t / 16;
    const int lr = t >> 1, lk = (t & 1) * 8;

    unsigned long long acc[4][8];
#pragma unroll
    for (int u = 0; u < 4; u++)
#pragma unroll
        for (int v = 0; v < 8; v++) acc[u][v] = 0ull;

    const bool vec = (K % 16 == 0);
    const int nchunks = (K + 15) / 16;
    float ra[8], rw[8];

    {
        const float* ap = A + (size_t)(m0 + lr) * astride + aoff + lk;
        const float* wp = W + (size_t)(n0 + lr) * K + lk;
        if (vec) {
            float4 a0 = *(const float4*)ap, a1 = *(const float4*)(ap + 4);
            float4 w0 = *(const float4*)wp, w1 = *(const float4*)(wp + 4);
            ra[0]=a0.x; ra[1]=a0.y; ra[2]=a0.z; ra[3]=a0.w; ra[4]=a1.x; ra[5]=a1.y; ra[6]=a1.z; ra[7]=a1.w;
            rw[0]=w0.x; rw[1]=w0.y; rw[2]=w0.z; rw[3]=w0.w; rw[4]=w1.x; rw[5]=w1.y; rw[6]=w1.z; rw[7]=w1.w;
        } else {
#pragma unroll
            for (int u = 0; u < 8; u++) {
                int k = lk + u;
                ra[u] = (k < K) ? ap[u] : 0.f;
                rw[u] = (k < K) ? wp[u] : 0.f;
            }
        }
    }
#pragma unroll
    for (int u = 0; u < 8; u++) { As[0][lk + u][lr] = ra[u]; Ws[0][lk + u][lr] = rw[u]; }
    __syncthreads();

    for (int c = 0; c < nchunks; c++) {
        if (c + 1 < nchunks) {
            int k0 = (c + 1) * 16;
            const float* ap = A + (size_t)(m0 + lr) * astride + aoff + k0 + lk;
            const float* wp = W + (size_t)(n0 + lr) * K + k0 + lk;
            if (vec) {
                float4 a0 = *(const float4*)ap, a1 = *(const float4*)(ap + 4);
                float4 w0 = *(const float4*)wp, w1 = *(const float4*)(wp + 4);
                ra[0]=a0.x; ra[1]=a0.y; ra[2]=a0.z; ra[3]=a0.w; ra[4]=a1.x; ra[5]=a1.y; ra[6]=a1.z; ra[7]=a1.w;
                rw[0]=w0.x; rw[1]=w0.y; rw[2]=w0.z; rw[3]=w0.w; rw[4]=w1.x; rw[5]=w1.y; rw[6]=w1.z; rw[7]=w1.w;
            } else {
#pragma unroll
                for (int u = 0; u < 8; u++) {
                    int k = k0 + lk + u;
                    ra[u] = (k < K) ? ap[u] : 0.f;
                    rw[u] = (k < K) ? wp[u] : 0.f;
                }
            }
        }

        const int s = c & 1;
#pragma unroll
        for (int k = 0; k < 16; k++) {
            ulonglong2 a01 = *(const ulonglong2*)&As[s][k][ty * 8];
            ulonglong2 a23 = *(const ulonglong2*)&As[s][k][ty * 8 + 4];
            unsigned long long a2[4] = {a01.x, a01.y, a23.x, a23.y};
            const float* wrow = &Ws[s][k][tx * 8];
            float4 w0 = *(const float4*)wrow;
            float4 w1 = *(const float4*)(wrow + 4);
            float wv[8] = {w0.x, w0.y, w0.z, w0.w, w1.x, w1.y, w1.z, w1.w};
#pragma unroll
            for (int v = 0; v < 8; v++) {
                unsigned long long wd = dup2(wv[v]);
#pragma unroll
                for (int u = 0; u < 4; u++) FMA2(acc[u][v], a2[u], wd);
            }
        }
        __syncthreads();
        if (c + 1 < nchunks) {
            const int sn = (c + 1) & 1;
#pragma unroll
            for (int u = 0; u < 8; u++) { As[sn][lk + u][lr] = ra[u]; Ws[sn][lk + u][lr] = rw[u]; }
            __syncthreads();
        }
    }

    float4 bias0, bias1;
    if (MODE == 1) {
        bias0 = *(const float4*)&bias[n0 + tx * 8];
        bias1 = *(const float4*)&bias[n0 + tx * 8 + 4];
    }
#pragma unroll
    for (int u = 0; u < 4; u++) {
        float2 cvals[8];
#pragma unroll
        for (int v = 0; v < 8; v++) cvals[v] = unpack2(acc[u][v]);
#pragma unroll
        for (int half = 0; half < 2; half++) {
            int m = m0 + ty * 8 + u * 2 + half;
            float o[8];
#pragma unroll
            for (int v = 0; v < 8; v++) o[v] = half ? cvals[v].y : cvals[v].x;
            if (MODE == 1) {
                o[0] = lrelu(o[0] + bias0.x); o[1] = lrelu(o[1] + bias0.y);
                o[2] = lrelu(o[2] + bias0.z); o[3] = lrelu(o[3] + bias0.w);
                o[4] = lrelu(o[4] + bias1.x); o[5] = lrelu(o[5] + bias1.y);
                o[6] = lrelu(o[6] + bias1.z); o[7] = lrelu(o[7] + bias1.w);
            }
            float* op = out + (size_t)m * Nout + n0 + tx * 8;
            *(float4*)op       = make_float4(o[0], o[1], o[2], o[3]);
            *(float4*)(op + 4) = make_float4(o[4], o[5], o[6], o[7]);
        }
    }
}

// ---------------- gather + max over k (256/O points per 256-thread block) --
template <int O>
__global__ void __launch_bounds__(256)
gathermax_k(const float* __restrict__ yz, const int* __restrict__ idx,
            const float* __restrict__ bias, float* __restrict__ feats, int choff)
{
    constexpr int P = 256 / O;
    const int t = threadIdx.x;
    const int bn0 = blockIdx.x * P;
    __shared__ int sidx[P * KNNK];
    if (t < P * KNNK) sidx[t] = idx[(size_t)bn0 * KNNK + t];
    __syncthreads();
    const int pl = t / O, o = t % O;
    const int bn = bn0 + pl;
    const int b = bn / NP, n = bn % NP;
    const float* yzb = yz + (size_t)b * NP * 2 * O;
    float z = yzb[(size_t)n * 2 * O + O + o] + bias[o];
    float m = -3.4e38f;
#pragma unroll 4
    for (int k = 0; k < KNNK; k++) {
        float v = yzb[(size_t)sidx[pl * KNNK + k] * 2 * O + o] + z;
        m = fmaxf(m, lrelu(v));
    }
    feats[(size_t)bn * 512 + choff + o] = m;
}

// ---------------- max/mean reduce over N ----------------
__global__ void reduce_k(const float* __restrict__ x5, float* __restrict__ map2,
                         float* __restrict__ outmap)
{
    int b = blockIdx.y;
    int o = blockIdx.x * 256 + threadIdx.x;
    const float* p = x5 + (size_t)b * NP * 1024 + o;
    float mx = -3.4e38f;
    float s0 = 0.f, s1 = 0.f, s2 = 0.f, s3 = 0.f;
    for (int n = 0; n < NP; n += 4) {
        float v0 = p[(size_t)(n + 0) * 1024];
        float v1 = p[(size_t)(n + 1) * 1024];
        float v2 = p[(size_t)(n + 2) * 1024];
        float v3 = p[(size_t)(n + 3) * 1024];
        mx = fmaxf(mx, fmaxf(fmaxf(v0, v1), fmaxf(v2, v3)));
        s0 += v0; s1 += v1; s2 += v2; s3 += v3;
    }
    float mean = ((s0 + s1) + (s2 + s3)) * (1.0f / NP);
    map2[b * 2080 + o] = mx;
    map2[b * 2080 + 1024 + o] = mean;
    outmap[b * 2048 + o] = mx;
    outmap[b * 2048 + 1024 + o] = mean;
}

// ---------------- pose branch ----------------
__global__ void pose_k(const float* __restrict__ pf, const float* __restrict__ Wpf,
                       const float* __restrict__ bpf, float* __restrict__ map2)
{
    int t = threadIdx.x;
    if (t >= BB * 32) return;
    int b = t / 32, j = t % 32;
    float s = 0.f;
    for (int c = 0; c < 6; c++) s += pf[b * 6 + c] * Wpf[j * 8 + c];
    s += bpf[j];
    map2[b * 2080 + 2048 + j] = lrelu(s);
}

// ---------------- small FC (thread per output) ----------------
template <int ACT>
__global__ void fc_k(const float* __restrict__ A, const float* __restrict__ W,
                     const float* __restrict__ bias, float* __restrict__ out,
                     int M, int K, int Nout)
{
    int e = blockIdx.x * blockDim.x + threadIdx.x;
    if (e >= M * Nout) return;
    int m = e / Nout, n = e % Nout;
    const float4* a4 = (const float4*)(A + (size_t)m * K);
    const float4* w4 = (const float4*)(W + (size_t)n * K);
    float s = 0.f;
    for (int c = 0; c < K / 4; c++) {
        float4 a = a4[c], w = w4[c];
        s += a.x * w.x; s += a.y * w.y; s += a.z * w.z; s += a.w * w.w;
    }
    s += bias[n];
    if (ACT) s = lrelu(s);
    out[e] = s;
}

// ---------------- host launch ----------------
extern "C" void kernel_launch(void* const* d_in, const int* in_sizes, int n_in,
                              void* d_out, int out_size)
{
    (void)in_sizes; (void)n_in; (void)out_size;
    const float* x   = (const float*)d_in[0];
    const float* pf  = (const float*)d_in[1];
    const float* W1  = (const float*)d_in[2];
    const float* g1  = (const float*)d_in[3];
    const float* b1  = (const float*)d_in[4];
    const float* W2  = (const float*)d_in[5];
    const float* g2  = (const float*)d_in[6];
    const float* b2  = (const float*)d_in[7];
    const float* W3  = (const float*)d_in[8];
    const float* g3  = (const float*)d_in[9];
    const float* b3  = (const float*)d_in[10];
    const float* W4  = (const float*)d_in[11];
    const float* g4  = (const float*)d_in[12];
    const float* b4  = (const float*)d_in[13];
    const float* W5  = (const float*)d_in[14];
    const float* g5  = (const float*)d_in[15];
    const float* b5  = (const float*)d_in[16];
    const float* Wp  = (const float*)d_in[17];
    const float* bp  = (const float*)d_in[18];
    const float* gp  = (const float*)d_in[19];
    const float* bpb = (const float*)d_in[20];
    const float* WL1 = (const float*)d_in[21];
    const float* bL1 = (const float*)d_in[22];
    const float* g6  = (const float*)d_in[23];
    const float* b6  = (const float*)d_in[24];
    const float* WL2 = (const float*)d_in[25];
    const float* bL2 = (const float*)d_in[26];
    const float* g7  = (const float*)d_in[27];
    const float* b7  = (const float*)d_in[28];
    const float* WL3 = (const float*)d_in[29];
    const float* bL3 = (const float*)d_in[30];

    float* out = (float*)d_out;          // [0,320): logits ; then map_
    float* outmap = out + BB * 40;

    float *p_xt, *p_feats, *p_yz, *p_x5, *p_map2, *p_h1, *p_h2;
    int* p_idx;
    float *p_WC1, *p_WC2, *p_WC3, *p_WC4, *p_W5f, *p_W6f, *p_b6f, *p_W7f, *p_b7f, *p_Wpf, *p_bpf;
    cudaGetSymbolAddress((void**)&p_xt, d_xt);
    cudaGetSymbolAddress((void**)&p_feats, d_feats);
    cudaGetSymbolAddress((void**)&p_yz, d_yz);
    cudaGetSymbolAddress((void**)&p_x5, d_x5);
    cudaGetSymbolAddress((void**)&p_idx, d_idx);
    cudaGetSymbolAddress((void**)&p_map2, d_map2);
    cudaGetSymbolAddress((void**)&p_h1, d_h1);
    cudaGetSymbolAddress((void**)&p_h2, d_h2);
    cudaGetSymbolAddress((void**)&p_WC1, d_WC1);
    cudaGetSymbolAddress((void**)&p_WC2, d_WC2);
    cudaGetSymbolAddress((void**)&p_WC3, d_WC3);
    cudaGetSymbolAddress((void**)&p_WC4, d_WC4);
    cudaGetSymbolAddress((void**)&p_W5f, d_W5f);
    cudaGetSymbolAddress((void**)&p_W6f, d_W6f);
    cudaGetSymbolAddress((void**)&p_b6f, d_b6f);
    cudaGetSymbolAddress((void**)&p_W7f, d_W7f);
    cudaGetSymbolAddress((void**)&p_b7f, d_b7f);
    cudaGetSymbolAddress((void**)&p_Wpf, d_Wpf);
    cudaGetSymbolAddress((void**)&p_bpf, d_bpf);

    const int M = BB * NP;  // 16384

    // 1) edge-conv weight folds  2) fc/scale folds  3) transpose
    prep_edge_all_k<<<(NE1 + NE2 + NE3 + NE4 + 255) / 256, 256>>>(
        W1, g1, W2, g2, W3, g3, W4, g4, p_WC1, p_WC2, p_WC3, p_WC4);
    prep_fc_all_k<<<(NF5 + NF6 + NF7 + NFP + 255) / 256, 256>>>(
        W5, g5, WL1, bL1, g6, b6, WL2, bL2, g7, b7, Wp, bp, gp, bpb,
        p_W5f, p_W6f, p_b6f, p_W7f, p_b7f, p_Wpf, p_bpf);
    transpose_k<<<(BB * 3 * NP + 255) / 256, 256>>>(x, p_xt);

    // knn smem: merge region NT*KNNK*8 bytes dominates all load regions
    constexpr int SMK = 256 * KNNK * 8;   // 40960

    // ---- layer 1 (C=3) -> feats[:, 0:64]   (knn1 = 4th launch, ncu-captured)
    knn_k<3, 32, 8, 128><<<dim3(NP / 32, BB), 256, SMK>>>(p_xt, 3, 0, p_idx);
    gemm2_k<0><<<dim3(1, M / 128), 256>>>(p_xt, 3, 0, p_WC1, nullptr, p_yz, 3, 128);
    gathermax_k<64><<<M / 4, 256>>>(p_yz, p_idx, b1, p_feats, 0);

    // ---- layer 2 (C=64) -> feats[:, 64:128]
    knn_k<64, 32, 8, 64><<<dim3(NP / 32, BB), 256, SMK>>>(p_feats, 512, 0, p_idx);
    gemm2_k<0><<<dim3(1, M / 128), 256>>>(p_feats, 512, 0, p_WC2, nullptr, p_yz, 64, 128);
    gathermax_k<64><<<M / 4, 256>>>(p_yz, p_idx, b2, p_feats, 64);

    // ---- layer 3 (C=64) -> feats[:, 128:256]
    knn_k<64, 32, 8, 64><<<dim3(NP / 32, BB), 256, SMK>>>(p_feats, 512, 64, p_idx);
    gemm2_k<0><<<dim3(2, M / 128), 256>>>(p_feats, 512, 64, p_WC3, nullptr, p_yz, 64, 256);
    gathermax_k<128><<<M / 2, 256>>>(p_yz, p_idx, b3, p_feats, 128);

    // ---- layer 4 (C=128) -> feats[:, 256:512]
    knn_k<128, 32, 8, 32><<<dim3(NP / 32, BB), 256, SMK>>>(p_feats, 512, 128, p_idx);
    gemm2_k<0><<<dim3(4, M / 128), 256>>>(p_feats, 512, 128, p_WC4, nullptr, p_yz, 128, 512);
    gathermax_k<256><<<M, 256>>>(p_yz, p_idx, b4, p_feats, 256);

    // ---- W5 conv + lrelu
    gemm2_k<1><<<dim3(8, M / 128), 256>>>(p_feats, 512, 0, p_W5f, b5, p_x5, 512, 1024);

    // ---- max/mean reduce -> map2[:, :2048] and map_ output
    reduce_k<<<dim3(4, BB), 256>>>(p_x5, p_map2, outmap);

    // ---- pose branch
    pose_k<<<1, 256>>>(pf, p_Wpf, p_bpf, p_map2);

    // ---- head
    fc_k<1><<<(BB * 512 + 255) / 256, 256>>>(p_map2, p_W6f, p_b6f, p_h1, BB, 2080, 512);
    fc_k<1><<<(BB * 256 + 255) / 256, 256>>>(p_h1, p_W7f, p_b7f, p_h2, BB, 512, 256);
    fc_k<0><<<(BB * 40 + 255) / 256, 256>>>(p_h2, WL3, bL3, out, BB, 256, 40);
}

// round 17
// speedup vs baseline: 2.0339x; 2.0339x over previous
#include <cuda_runtime.h>
#include <cuda_bf16.h>
#include <math.h>
#include <stdint.h>

#define BB 8
#define NP 2048
#define KNNK 20

// ---------------- static scratch (no allocations allowed) ----------------
__device__ __align__(16) float d_xt   [BB * NP * 3];
__device__ __align__(16) float d_feats[BB * NP * 512];   // x1|x2|x3|x4 at ch 0/64/128/256
__device__ __align__(16) float d_yz   [BB * NP * 512];   // per-layer [Y|Z], 2O <= 512
__device__ __align__(16) float d_x5   [BB * NP * 1024];
__device__ __align__(16) float d_xx   [BB * NP];
__device__            int    d_idx  [BB * NP * KNNK];
__device__ __align__(16) float d_map2 [BB * 2080];
__device__ __align__(16) float d_h1   [BB * 512];
__device__ __align__(16) float d_h2   [BB * 256];
// folded weights
__device__ __align__(16) float d_WC1[2 * 64 * 3];
__device__ __align__(16) float d_WC2[2 * 64 * 64];
__device__ __align__(16) float d_WC3[2 * 128 * 64];
__device__ __align__(16) float d_WC4[2 * 256 * 128];
__device__ __align__(16) float d_W5f[1024 * 512];
__device__ __align__(16) float d_W6f[512 * 2080];
__device__ __align__(16) float d_b6f[512];
__device__ __align__(16) float d_W7f[256 * 512];
__device__ __align__(16) float d_b7f[256];
__device__ __align__(16) float d_Wpf[32 * 8];
__device__ __align__(16) float d_bpf[32];

__device__ __forceinline__ float lrelu(float v) { return v >= 0.f ? v : 0.2f * v; }

// packed fp32x2 helpers (Blackwell FFMA2)
#define FMA2(acc, a, b) asm("fma.rn.f32x2 %0, %1, %2, %0;" : "+l"(acc) : "l"(a), "l"(b))
__device__ __forceinline__ unsigned long long dup2(float w) {
    unsigned long long r;
    asm("mov.b64 %0, {%1, %1};" : "=l"(r) : "f"(w));
    return r;
}
__device__ __forceinline__ unsigned long long pack2(float a, float b) {
    unsigned long long r;
    asm("mov.b64 %0, {%1, %2};" : "=l"(r) : "f"(a), "f"(b));
    return r;
}
__device__ __forceinline__ float2 unpack2(unsigned long long v) {
    float2 f;
    asm("mov.b64 {%0, %1}, %2;" : "=f"(f.x), "=f"(f.y) : "l"(v));
    return f;
}

// ---------------- merged weight folding (edge convs) ----------------
__device__ __forceinline__ void fold_edge(const float* W, const float* g,
                                          float* Wcat, int O, int C, int e)
{
    int o = e / C, c = e % C;
    float s = g[o] * rsqrtf(1.0f + 1e-5f);
    float wa = W[o * 2 * C + c];
    float wb = W[o * 2 * C + C + c];
    Wcat[o * C + c] = s * wa;
    Wcat[(O + o) * C + c] = s * (wb - wa);
}

#define NE1 (64 * 3)
#define NE2 (64 * 64)
#define NE3 (128 * 64)
#define NE4 (256 * 128)

__global__ void prep_edge_all_k(const float* __restrict__ W1, const float* __restrict__ g1,
                                const float* __restrict__ W2, const float* __restrict__ g2,
                                const float* __restrict__ W3, const float* __restrict__ g3,
                                const float* __restrict__ W4, const float* __restrict__ g4,
                                float* __restrict__ WC1, float* __restrict__ WC2,
                                float* __restrict__ WC3, float* __restrict__ WC4)
{
    int e = blockIdx.x * blockDim.x + threadIdx.x;
    if (e < NE1) { fold_edge(W1, g1, WC1, 64, 3, e); return; }
    e -= NE1;
    if (e < NE2) { fold_edge(W2, g2, WC2, 64, 64, e); return; }
    e -= NE2;
    if (e < NE3) { fold_edge(W3, g3, WC3, 128, 64, e); return; }
    e -= NE3;
    if (e < NE4) { fold_edge(W4, g4, WC4, 256, 128, e); return; }
}

// ---------------- merged fc/scale folding ----------------
#define NF5 (1024 * 512)
#define NF6 (512 * 2080)
#define NF7 (256 * 512)
#define NFP (32 * 6)

__global__ void prep_fc_all_k(const float* __restrict__ W5, const float* __restrict__ g5,
                              const float* __restrict__ WL1, const float* __restrict__ bL1,
                              const float* __restrict__ g6, const float* __restrict__ b6,
                              const float* __restrict__ WL2, const float* __restrict__ bL2,
                              const float* __restrict__ g7, const float* __restrict__ b7,
                              const float* __restrict__ Wp, const float* __restrict__ bp,
                              const float* __restrict__ gp, const float* __restrict__ bpb,
                              float* __restrict__ W5f,
                              float* __restrict__ W6f, float* __restrict__ b6f,
                              float* __restrict__ W7f, float* __restrict__ b7f,
                              float* __restrict__ Wpf, float* __restrict__ bpf)
{
    int e = blockIdx.x * blockDim.x + threadIdx.x;
    if (e < NF5) {
        int o = e / 512;
        W5f[e] = (g5[o] * rsqrtf(1.0f + 1e-5f)) * W5[e];
        return;
    }
    e -= NF5;
    if (e < NF6) {
        int o = e / 2080, c = e % 2080;
        float s = g6[o] * rsqrtf(1.0f + 1e-5f);
        W6f[e] = s * WL1[e];
        if (c == 0) b6f[o] = s * bL1[o] + b6[o];
        return;
    }
    e -= NF6;
    if (e < NF7) {
        int o = e / 512, c = e % 512;
        float s = g7[o] * rsqrtf(1.0f + 1e-5f);
        W7f[e] = s * WL2[e];
        if (c == 0) b7f[o] = s * bL2[o] + b7[o];
        return;
    }
    e -= NF7;
    if (e < NFP) {
        int o = e / 6, c = e % 6;
        float s = gp[o] * rsqrtf(1.0f + 1e-5f);
        Wpf[o * 8 + c] = s * Wp[e];
        if (c == 0) bpf[o] = s * bp[o] + bpb[o];
        return;
    }
}

// ---------------- transpose (B,3,N) -> (B,N,3) ----------------
__global__ void transpose_k(const float* __restrict__ x, float* __restrict__ xt)
{
    int gid = blockIdx.x * blockDim.x + threadIdx.x;
    if (gid >= BB * 3 * NP) return;
    int n = gid % NP;
    int c = (gid / NP) % 3;
    int b = gid / (3 * NP);
    xt[(b * NP + n) * 3 + c] = x[gid];
}

// ---------------- squared norms (bitwise-identical FMA2 chain as knn dot) --
__global__ void xx_k(const float* __restrict__ in, int instride, int inoff, int C,
                     float* __restrict__ xx)
{
    int r = blockIdx.x * blockDim.x + threadIdx.x;
    if (r >= BB * NP) return;
    const float* p = in + (size_t)r * instride + inoff;
    unsigned long long acc = 0ull;
    for (int c4 = 0; c4 < C / 4; c4++) {
        ulonglong2 a = *(const ulonglong2*)(p + 4 * c4);
        FMA2(acc, a.x, a.x);
        FMA2(acc, a.y, a.y);
    }
    float2 f = unpack2(acc);
    xx[r] = f.x + f.y;
}

// ---------------- fused distance + top-20 KNN ----------------
// TI queries/block, 4 threads/query. Conflict-free padded strides (bank step
// 4 mod 32 over 8-lane phases). Warp-synchronized insert with 4-slot SMEM
// stash: unconditional (pd,j) store at slot scnt (conflict-free [slot][NT]
// layout), ballot per candidate, flush-all when any lane fills.
// Self-distance exactly 0: xx chain == dot chain bitwise.
template <int C> struct KnnPad { static constexpr int Cp = C + 4; };
template <> struct KnnPad<3>   { static constexpr int Cp = 4; };
template <> struct KnnPad<64>  { static constexpr int Cp = 68; };
template <> struct KnnPad<128> { static constexpr int Cp = 132; };

template <int C, int TI>
__global__ void __launch_bounds__(TI * 4)
knn_k(const float* __restrict__ in, int instride, int inoff,
      const float* __restrict__ xx, int* __restrict__ idxout)
{
    constexpr int Cp  = KnnPad<C>::Cp;
    constexpr int TJ4 = TI / 4;
    constexpr int NT  = TI * 4;
    constexpr int QS  = (C == 3) ? 0 : TI * Cp;
    extern __shared__ float sm[];
    float* stash_f = sm;                       // [4][NT]
    int*   stash_i = (int*)(sm + 4 * NT);      // [4][NT]
    float* s_xi  = sm + 8 * NT;
    float* s_xj  = s_xi + QS;
    float* s_xxj = s_xj + ((C == 3) ? TI * 4 : TI * Cp);

    const int b  = blockIdx.y;
    const int n0 = blockIdx.x * TI;
    const int t  = threadIdx.x;
    const int i  = t % TI;
    const int q  = t / TI;

    // ---- query + its norm
    unsigned long long aq0 = 0ull, aq1 = 0ull;
    float xxi;
    if (C == 3) {
        const float* qp = in + (size_t)(b * NP + n0 + i) * instride + inoff;
        aq0 = pack2(qp[0], qp[1]);
        aq1 = pack2(qp[2], 0.f);
        unsigned long long acc = 0ull;
        FMA2(acc, aq0, aq0);
        FMA2(acc, aq1, aq1);
        float2 f = unpack2(acc);
        xxi = f.x + f.y;
    } else {
        for (int e = t; e < TI * C / 4; e += NT) {
            int r = e / (C / 4), c4 = e % (C / 4);
            *(float4*)&s_xi[r * Cp + 4 * c4] =
                *(const float4*)(in + (size_t)(b * NP + n0 + r) * instride + inoff + 4 * c4);
        }
        xxi = xx[b * NP + n0 + i];
    }

    float kv[KNNK];
    int   kj[KNNK];
#pragma unroll
    for (int s = 0; s < KNNK; s++) { kv[s] = -3.4e38f; kj[s] = 0x7fffffff; }

    int scnt = 0;

    auto flush = [&]() {
#pragma unroll
        for (int slot = 0; slot < 4; slot++) {
            float nv = stash_f[slot * NT + t];
            int   nj = stash_i[slot * NT + t];
            bool a = (scnt > slot) && (nv > kv[KNNK - 1]);
            kv[KNNK - 1] = a ? nv : kv[KNNK - 1];
            kj[KNNK - 1] = a ? nj : kj[KNNK - 1];
#pragma unroll
            for (int s = KNNK - 1; s > 0; s--) {
                bool sw = kv[s] > kv[s - 1];
                float tv = kv[s - 1]; int tj = kj[s - 1];
                kv[s - 1] = sw ? kv[s] : tv;
                kj[s - 1] = sw ? kj[s] : tj;
                kv[s]     = sw ? tv : kv[s];
                kj[s]     = sw ? tj : kj[s];
            }
        }
        scnt = 0;
    };

    auto accept = [&](float pd, int j) {
        int off = scnt * NT + t;         // scnt <= 3 always
        stash_f[off] = pd;               // unconditional, conflict-free
        stash_i[off] = j;
        bool ac = pd > kv[KNNK - 1];
        scnt += ac ? 1 : 0;
        if (__ballot_sync(0xffffffffu, scnt >= 4)) flush();
    };

    for (int j0 = 0; j0 < NP; j0 += TI) {
        __syncthreads();
        if (C == 3) {
            for (int e = t; e < TI; e += NT) {
                const float* rp = in + (size_t)(b * NP + j0 + e) * instride + inoff;
                float v0 = rp[0], v1 = rp[1], v2 = rp[2];
                s_xj[e * 4 + 0] = v0;
                s_xj[e * 4 + 1] = v1;
                s_xj[e * 4 + 2] = v2;
                s_xj[e * 4 + 3] = 0.f;
                float sx = 0.f, sy = 0.f;
                sx += v0 * v0;
                sy += v1 * v1;
                sx += v2 * v2;
                s_xxj[e] = sx + sy;
            }
        } else {
            for (int e = t; e < TI * C / 4; e += NT) {
                int r = e / (C / 4), c4 = e % (C / 4);
                *(float4*)&s_xj[r * Cp + 4 * c4] =
                    *(const float4*)(in + (size_t)(b * NP + j0 + r) * instride + inoff + 4 * c4);
            }
            for (int e = t; e < TI; e += NT) s_xxj[e] = xx[b * NP + j0 + e];
        }
        __syncthreads();

        if (C == 3) {
#pragma unroll 1
            for (int jj = 0; jj < TJ4; jj++) {
                int jl = q * TJ4 + jj;
                ulonglong2 w = *(const ulonglong2*)&s_xj[jl * 4];
                unsigned long long acc = 0ull;
                FMA2(acc, aq0, w.x);
                FMA2(acc, aq1, w.y);
                float2 f = unpack2(acc);
                float pd = 2.f * (f.x + f.y) - xxi - s_xxj[jl];
                accept(pd, j0 + jl);
            }
        } else {
            // sub-batch jj in chunks of 8 to bound dacc register pressure
#pragma unroll 1
            for (int jb = 0; jb < TJ4; jb += 8) {
                unsigned long long dacc[8];
#pragma unroll
                for (int jj = 0; jj < 8; jj++) dacc[jj] = 0ull;
#pragma unroll 2
                for (int c4 = 0; c4 < C / 4; c4++) {
                    ulonglong2 a = *(const ulonglong2*)&s_xi[i * Cp + 4 * c4];
#pragma unroll
                    for (int jj = 0; jj < 8; jj++) {
                        ulonglong2 w = *(const ulonglong2*)&s_xj[(q * TJ4 + jb + jj) * Cp + 4 * c4];
                        FMA2(dacc[jj], a.x, w.x);
                        FMA2(dacc[jj], a.y, w.y);
                    }
                }
#pragma unroll 1
                for (int jj = 0; jj < 8; jj++) {
                    int jl = q * TJ4 + jb + jj;
                    float2 f = unpack2(dacc[jj]);
                    float pd = 2.f * (f.x + f.y) - xxi - s_xxj[jl];
                    accept(pd, j0 + jl);
                }
            }
        }
    }

    flush();  // drain residual stash

    __syncthreads();  // reuse smem for merge
    float* s_mv = sm;
    int*   s_mi = (int*)(sm + NT * KNNK);
    {
        int base = (i * 4 + q) * KNNK;
#pragma unroll
        for (int s = 0; s < KNNK; s++) { s_mv[base + s] = kv[s]; s_mi[base + s] = kj[s]; }
    }
    __syncthreads();

    if (t < TI) {
        int base = t * 4 * KNNK;
        int p[4] = {0, 0, 0, 0};
        int* orow = idxout + (size_t)(b * NP + n0 + t) * KNNK;
        for (int s = 0; s < KNNK; s++) {
            float bv = -3.4e38f; int bj = 0x7fffffff; int bq = 0;
#pragma unroll
            for (int qq = 0; qq < 4; qq++) {
                float v  = s_mv[base + qq * KNNK + p[qq]];
                int   jv = s_mi[base + qq * KNNK + p[qq]];
                if (v > bv || (v == bv && jv < bj)) { bv = v; bj = jv; bq = qq; }
            }
            orow[s] = bj;
#pragma unroll
            for (int qq = 0; qq < 4; qq++) p[qq] += (bq == qq) ? 1 : 0;
        }
    }
}

// ---------------- FFMA2 GEMM: out[M x Nout] = A[M x K] @ W[Nout x K]^T ----
template <int MODE>
__global__ void __launch_bounds__(256, 2)
gemm2_k(const float* __restrict__ A, int astride, int aoff,
        const float* __restrict__ W, const float* __restrict__ bias,
        float* __restrict__ out, int K, int Nout)
{
    __shared__ __align__(16) float As[2][16][132];
    __shared__ __align__(16) float Ws[2][16][132];
    const int m0 = blockIdx.y * 128, n0 = blockIdx.x * 128;
    const int t  = threadIdx.x;
    const int tx = t % 16, ty = t / 16;
    const int lr = t >> 1, lk = (t & 1) * 8;

    unsigned long long acc[4][8];
#pragma unroll
    for (int u = 0; u < 4; u++)
#pragma unroll
        for (int v = 0; v < 8; v++) acc[u][v] = 0ull;

    const bool vec = (K % 16 == 0);
    const int nchunks = (K + 15) / 16;
    float ra[8], rw[8];

    {
        const float* ap = A + (size_t)(m0 + lr) * astride + aoff + lk;
        const float* wp = W + (size_t)(n0 + lr) * K + lk;
        if (vec) {
            float4 a0 = *(const float4*)ap, a1 = *(const float4*)(ap + 4);
            float4 w0 = *(const float4*)wp, w1 = *(const float4*)(wp + 4);
            ra[0]=a0.x; ra[1]=a0.y; ra[2]=a0.z; ra[3]=a0.w; ra[4]=a1.x; ra[5]=a1.y; ra[6]=a1.z; ra[7]=a1.w;
            rw[0]=w0.x; rw[1]=w0.y; rw[2]=w0.z; rw[3]=w0.w; rw[4]=w1.x; rw[5]=w1.y; rw[6]=w1.z; rw[7]=w1.w;
        } else {
#pragma unroll
            for (int u = 0; u < 8; u++) {
                int k = lk + u;
                ra[u] = (k < K) ? ap[u] : 0.f;
                rw[u] = (k < K) ? wp[u] : 0.f;
            }
        }
    }
#pragma unroll
    for (int u = 0; u < 8; u++) { As[0][lk + u][lr] = ra[u]; Ws[0][lk + u][lr] = rw[u]; }
    __syncthreads();

    for (int c = 0; c < nchunks; c++) {
        if (c + 1 < nchunks) {
            int k0 = (c + 1) * 16;
            const float* ap = A + (size_t)(m0 + lr) * astride + aoff + k0 + lk;
            const float* wp = W + (size_t)(n0 + lr) * K + k0 + lk;
            if (vec) {
                float4 a0 = *(const float4*)ap, a1 = *(const float4*)(ap + 4);
                float4 w0 = *(const float4*)wp, w1 = *(const float4*)(wp + 4);
                ra[0]=a0.x; ra[1]=a0.y; ra[2]=a0.z; ra[3]=a0.w; ra[4]=a1.x; ra[5]=a1.y; ra[6]=a1.z; ra[7]=a1.w;
                rw[0]=w0.x; rw[1]=w0.y; rw[2]=w0.z; rw[3]=w0.w; rw[4]=w1.x; rw[5]=w1.y; rw[6]=w1.z; rw[7]=w1.w;
            } else {
#pragma unroll
                for (int u = 0; u < 8; u++) {
                    int k = k0 + lk + u;
                    ra[u] = (k < K) ? ap[u] : 0.f;
                    rw[u] = (k < K) ? wp[u] : 0.f;
                }
            }
        }

        const int s = c & 1;
#pragma unroll
        for (int k = 0; k < 16; k++) {
            ulonglong2 a01 = *(const ulonglong2*)&As[s][k][ty * 8];
            ulonglong2 a23 = *(const ulonglong2*)&As[s][k][ty * 8 + 4];
            unsigned long long a2[4] = {a01.x, a01.y, a23.x, a23.y};
            const float* wrow = &Ws[s][k][tx * 8];
            float4 w0 = *(const float4*)wrow;
            float4 w1 = *(const float4*)(wrow + 4);
            float wv[8] = {w0.x, w0.y, w0.z, w0.w, w1.x, w1.y, w1.z, w1.w};
#pragma unroll
            for (int v = 0; v < 8; v++) {
                unsigned long long wd = dup2(wv[v]);
#pragma unroll
                for (int u = 0; u < 4; u++) FMA2(acc[u][v], a2[u], wd);
            }
        }
        __syncthreads();
        if (c + 1 < nchunks) {
            const int sn = (c + 1) & 1;
#pragma unroll
            for (int u = 0; u < 8; u++) { As[sn][lk + u][lr] = ra[u]; Ws[sn][lk + u][lr] = rw[u]; }
            __syncthreads();
        }
    }

    float4 bias0, bias1;
    if (MODE == 1) {
        bias0 = *(const float4*)&bias[n0 + tx * 8];
        bias1 = *(const float4*)&bias[n0 + tx * 8 + 4];
    }
#pragma unroll
    for (int u = 0; u < 4; u++) {
        float2 cvals[8];
#pragma unroll
        for (int v = 0; v < 8; v++) cvals[v] = unpack2(acc[u][v]);
#pragma unroll
        for (int half = 0; half < 2; half++) {
            int m = m0 + ty * 8 + u * 2 + half;
            float o[8];
#pragma unroll
            for (int v = 0; v < 8; v++) o[v] = half ? cvals[v].y : cvals[v].x;
            if (MODE == 1) {
                o[0] = lrelu(o[0] + bias0.x); o[1] = lrelu(o[1] + bias0.y);
                o[2] = lrelu(o[2] + bias0.z); o[3] = lrelu(o[3] + bias0.w);
                o[4] = lrelu(o[4] + bias1.x); o[5] = lrelu(o[5] + bias1.y);
                o[6] = lrelu(o[6] + bias1.z); o[7] = lrelu(o[7] + bias1.w);
            }
            float* op = out + (size_t)m * Nout + n0 + tx * 8;
            *(float4*)op       = make_float4(o[0], o[1], o[2], o[3]);
            *(float4*)(op + 4) = make_float4(o[4], o[5], o[6], o[7]);
        }
    }
}

// ---------------- gather + max over k (256/O points per 256-thread block) --
template <int O>
__global__ void __launch_bounds__(256)
gathermax_k(const float* __restrict__ yz, const int* __restrict__ idx,
            const float* __restrict__ bias, float* __restrict__ feats, int choff)
{
    constexpr int P = 256 / O;
    const int t = threadIdx.x;
    const int bn0 = blockIdx.x * P;
    __shared__ int sidx[P * KNNK];
    if (t < P * KNNK) sidx[t] = idx[(size_t)bn0 * KNNK + t];
    __syncthreads();
    const int pl = t / O, o = t % O;
    const int bn = bn0 + pl;
    const int b = bn / NP, n = bn % NP;
    const float* yzb = yz + (size_t)b * NP * 2 * O;
    float z = yzb[(size_t)n * 2 * O + O + o] + bias[o];
    float m = -3.4e38f;
#pragma unroll 4
    for (int k = 0; k < KNNK; k++) {
        float v = yzb[(size_t)sidx[pl * KNNK + k] * 2 * O + o] + z;
        m = fmaxf(m, lrelu(v));
    }
    feats[(size_t)bn * 512 + choff + o] = m;
}

// ---------------- max/mean reduce over N ----------------
__global__ void reduce_k(const float* __restrict__ x5, float* __restrict__ map2,
                         float* __restrict__ outmap)
{
    int b = blockIdx.y;
    int o = blockIdx.x * 256 + threadIdx.x;
    const float* p = x5 + (size_t)b * NP * 1024 + o;
    float mx = -3.4e38f;
    float s0 = 0.f, s1 = 0.f, s2 = 0.f, s3 = 0.f;
    for (int n = 0; n < NP; n += 4) {
        float v0 = p[(size_t)(n + 0) * 1024];
        float v1 = p[(size_t)(n + 1) * 1024];
        float v2 = p[(size_t)(n + 2) * 1024];
        float v3 = p[(size_t)(n + 3) * 1024];
        mx = fmaxf(mx, fmaxf(fmaxf(v0, v1), fmaxf(v2, v3)));
        s0 += v0; s1 += v1; s2 += v2; s3 += v3;
    }
    float mean = ((s0 + s1) + (s2 + s3)) * (1.0f / NP);
    map2[b * 2080 + o] = mx;
    map2[b * 2080 + 1024 + o] = mean;
    outmap[b * 2048 + o] = mx;
    outmap[b * 2048 + 1024 + o] = mean;
}

// ---------------- pose branch ----------------
__global__ void pose_k(const float* __restrict__ pf, const float* __restrict__ Wpf,
                       const float* __restrict__ bpf, float* __restrict__ map2)
{
    int t = threadIdx.x;
    if (t >= BB * 32) return;
    int b = t / 32, j = t % 32;
    float s = 0.f;
    for (int c = 0; c < 6; c++) s += pf[b * 6 + c] * Wpf[j * 8 + c];
    s += bpf[j];
    map2[b * 2080 + 2048 + j] = lrelu(s);
}

// ---------------- small FC (thread per output) ----------------
template <int ACT>
__global__ void fc_k(const float* __restrict__ A, const float* __restrict__ W,
                     const float* __restrict__ bias, float* __restrict__ out,
                     int M, int K, int Nout)
{
    int e = blockIdx.x * blockDim.x + threadIdx.x;
    if (e >= M * Nout) return;
    int m = e / Nout, n = e % Nout;
    const float4* a4 = (const float4*)(A + (size_t)m * K);
    const float4* w4 = (const float4*)(W + (size_t)n * K);
    float s = 0.f;
    for (int c = 0; c < K / 4; c++) {
        float4 a = a4[c], w = w4[c];
        s += a.x * w.x; s += a.y * w.y; s += a.z * w.z; s += a.w * w.w;
    }
    s += bias[n];
    if (ACT) s = lrelu(s);
    out[e] = s;
}

// ---------------- host launch ----------------
extern "C" void kernel_launch(void* const* d_in, const int* in_sizes, int n_in,
                              void* d_out, int out_size)
{
    (void)in_sizes; (void)n_in; (void)out_size;
    const float* x   = (const float*)d_in[0];
    const float* pf  = (const float*)d_in[1];
    const float* W1  = (const float*)d_in[2];
    const float* g1  = (const float*)d_in[3];
    const float* b1  = (const float*)d_in[4];
    const float* W2  = (const float*)d_in[5];
    const float* g2  = (const float*)d_in[6];
    const float* b2  = (const float*)d_in[7];
    const float* W3  = (const float*)d_in[8];
    const float* g3  = (const float*)d_in[9];
    const float* b3  = (const float*)d_in[10];
    const float* W4  = (const float*)d_in[11];
    const float* g4  = (const float*)d_in[12];
    const float* b4  = (const float*)d_in[13];
    const float* W5  = (const float*)d_in[14];
    const float* g5  = (const float*)d_in[15];
    const float* b5  = (const float*)d_in[16];
    const float* Wp  = (const float*)d_in[17];
    const float* bp  = (const float*)d_in[18];
    const float* gp  = (const float*)d_in[19];
    const float* bpb = (const float*)d_in[20];
    const float* WL1 = (const float*)d_in[21];
    const float* bL1 = (const float*)d_in[22];
    const float* g6  = (const float*)d_in[23];
    const float* b6  = (const float*)d_in[24];
    const float* WL2 = (const float*)d_in[25];
    const float* bL2 = (const float*)d_in[26];
    const float* g7  = (const float*)d_in[27];
    const float* b7  = (const float*)d_in[28];
    const float* WL3 = (const float*)d_in[29];
    const float* bL3 = (const float*)d_in[30];

    float* out = (float*)d_out;          // [0,320): logits ; then map_
    float* outmap = out + BB * 40;

    float *p_xt, *p_feats, *p_yz, *p_x5, *p_xx, *p_map2, *p_h1, *p_h2;
    int* p_idx;
    float *p_WC1, *p_WC2, *p_WC3, *p_WC4, *p_W5f, *p_W6f, *p_b6f, *p_W7f, *p_b7f, *p_Wpf, *p_bpf;
    cudaGetSymbolAddress((void**)&p_xt, d_xt);
    cudaGetSymbolAddress((void**)&p_feats, d_feats);
    cudaGetSymbolAddress((void**)&p_yz, d_yz);
    cudaGetSymbolAddress((void**)&p_x5, d_x5);
    cudaGetSymbolAddress((void**)&p_xx, d_xx);
    cudaGetSymbolAddress((void**)&p_idx, d_idx);
    cudaGetSymbolAddress((void**)&p_map2, d_map2);
    cudaGetSymbolAddress((void**)&p_h1, d_h1);
    cudaGetSymbolAddress((void**)&p_h2, d_h2);
    cudaGetSymbolAddress((void**)&p_WC1, d_WC1);
    cudaGetSymbolAddress((void**)&p_WC2, d_WC2);
    cudaGetSymbolAddress((void**)&p_WC3, d_WC3);
    cudaGetSymbolAddress((void**)&p_WC4, d_WC4);
    cudaGetSymbolAddress((void**)&p_W5f, d_W5f);
    cudaGetSymbolAddress((void**)&p_W6f, d_W6f);
    cudaGetSymbolAddress((void**)&p_b6f, d_b6f);
    cudaGetSymbolAddress((void**)&p_W7f, d_W7f);
    cudaGetSymbolAddress((void**)&p_b7f, d_b7f);
    cudaGetSymbolAddress((void**)&p_Wpf, d_Wpf);
    cudaGetSymbolAddress((void**)&p_bpf, d_bpf);

    const int M = BB * NP;  // 16384

    // 1) edge-conv weight folds  2) fc/scale folds  3) transpose
    prep_edge_all_k<<<(NE1 + NE2 + NE3 + NE4 + 255) / 256, 256>>>(
        W1, g1, W2, g2, W3, g3, W4, g4, p_WC1, p_WC2, p_WC3, p_WC4);
    prep_fc_all_k<<<(NF5 + NF6 + NF7 + NFP + 255) / 256, 256>>>(
        W5, g5, WL1, bL1, g6, b6, WL2, bL2, g7, b7, Wp, bp, gp, bpb,
        p_W5f, p_W6f, p_b6f, p_W7f, p_b7f, p_Wpf, p_bpf);
    transpose_k<<<(BB * 3 * NP + 255) / 256, 256>>>(x, p_xt);

    // knn smem = max(stash + tiles, merge)
    constexpr int LAY3   = (8 * 256 + 64 * 4 + 64) * 4;                 //  9472
    constexpr int LAY64  = (8 * 256 + 2 * 64 * KnnPad<64>::Cp + 64) * 4;   // 43264
    constexpr int LAY128 = (8 * 128 + 2 * 32 * KnnPad<128>::Cp + 32) * 4;  // 38016
    constexpr int MERGE64 = 256 * KNNK * 8;   // 40960
    constexpr int MERGE32 = 128 * KNNK * 8;   // 20480
    const int SM3   = LAY3   > MERGE64 ? LAY3   : MERGE64;
    const int SM64  = LAY64  > MERGE64 ? LAY64  : MERGE64;
    const int SM128 = LAY128 > MERGE32 ? LAY128 : MERGE32;

    // ---- layer 1 (C=3) -> feats[:, 0:64]   (knn1 = 4th launch, ncu-captured)
    knn_k<3, 64><<<dim3(NP / 64, BB), 256, SM3>>>(p_xt, 3, 0, p_xx, p_idx);
    gemm2_k<0><<<dim3(1, M / 128), 256>>>(p_xt, 3, 0, p_WC1, nullptr, p_yz, 3, 128);
    gathermax_k<64><<<M / 4, 256>>>(p_yz, p_idx, b1, p_feats, 0);

    // ---- layer 2 (C=64) -> feats[:, 64:128]
    xx_k<<<(M + 255) / 256, 256>>>(p_feats, 512, 0, 64, p_xx);
    knn_k<64, 64><<<dim3(NP / 64, BB), 256, SM64>>>(p_feats, 512, 0, p_xx, p_idx);
    gemm2_k<0><<<dim3(1, M / 128), 256>>>(p_feats, 512, 0, p_WC2, nullptr, p_yz, 64, 128);
    gathermax_k<64><<<M / 4, 256>>>(p_yz, p_idx, b2, p_feats, 64);

    // ---- layer 3 (C=64) -> feats[:, 128:256]
    xx_k<<<(M + 255) / 256, 256>>>(p_feats, 512, 64, 64, p_xx);
    knn_k<64, 64><<<dim3(NP / 64, BB), 256, SM64>>>(p_feats, 512, 64, p_xx, p_idx);
    gemm2_k<0><<<dim3(2, M / 128), 256>>>(p_feats, 512, 64, p_WC3, nullptr, p_yz, 64, 256);
    gathermax_k<128><<<M / 2, 256>>>(p_yz, p_idx, b3, p_feats, 128);

    // ---- layer 4 (C=128) -> feats[:, 256:512]
    xx_k<<<(M + 255) / 256, 256>>>(p_feats, 512, 128, 128, p_xx);
    knn_k<128, 32><<<dim3(NP / 32, BB), 128, SM128>>>(p_feats, 512, 128, p_xx, p_idx);
    gemm2_k<0><<<dim3(4, M / 128), 256>>>(p_feats, 512, 128, p_WC4, nullptr, p_yz, 128, 512);
    gathermax_k<256><<<M, 256>>>(p_yz, p_idx, b4, p_feats, 256);

    // ---- W5 conv + lrelu
    gemm2_k<1><<<dim3(8, M / 128), 256>>>(p_feats, 512, 0, p_W5f, b5, p_x5, 512, 1024);

    // ---- max/mean reduce -> map2[:, :2048] and map_ output
    reduce_k<<<dim3(4, BB), 256>>>(p_x5, p_map2, outmap);

    // ---- pose branch
    pose_k<<<1, 256>>>(pf, p_Wpf, p_bpf, p_map2);

    // ---- head
    fc_k<1><<<(BB * 512 + 255) / 256, 256>>>(p_map2, p_W6f, p_b6f, p_h1, BB, 2080, 512);
    fc_k<1><<<(BB * 256 + 255) / 256, 256>>>(p_h1, p_W7f, p_b7f, p_h2, BB, 512, 256);
    fc_k<0><<<(BB * 40 + 255) / 256, 256>>>(p_h2, WL3, bL3, out, BB, 256, 40);
}